// round 8
// baseline (speedup 1.0000x reference)
#include <cuda_runtime.h>
#include <cuda_bf16.h>
#include <math.h>
#include <stdint.h>

#define NN 50000
#define NE 500000
#define DD 128
#define NB_SCALE 98
#define NCHUNK 26
#define NBLK 196   // ceil(50000/256)

// ---------------- device scratch ----------------
__device__ int   g_deg[NN];
__device__ int   g_pos[NN];
__device__ int   g_ptr[NN];        // scanA: block-local inclusive
__device__ int   g_ptr2[NN + 1];   // global exclusive (final CSR)
__device__ int   g_bsum[NBLK];
__device__ int   g_ssrc[NE];
__device__ int   g_srel[NE];
__device__ float g_sw[NE];
__device__ float g_scale[NN];
__device__ float g_partial[128];
__device__ float g_feats[(size_t)NN * 512];
__device__ float g_xa[(size_t)NN * DD];
__device__ float g_xb[(size_t)NN * DD];
__device__ __nv_bfloat16 g_Bhi[4 * NCHUNK * 8192];
__device__ __nv_bfloat16 g_Blo[4 * NCHUNK * 8192];

__device__ __forceinline__ uint32_t smem_u32(const void* p) {
    uint32_t a;
    asm("{ .reg .u64 t; cvta.to.shared.u64 t, %1; cvt.u32.u64 %0, t; }" : "=r"(a) : "l"(p));
    return a;
}
__device__ __forceinline__ void ldm_x4(uint32_t addr, uint32_t* r) {
    asm volatile("ldmatrix.sync.aligned.m8n8.x4.shared.b16 {%0,%1,%2,%3}, [%4];"
                 : "=r"(r[0]), "=r"(r[1]), "=r"(r[2]), "=r"(r[3]) : "r"(addr));
}
__device__ __forceinline__ void mma16816(float* c, const uint32_t* a, uint32_t b0, uint32_t b1) {
    asm volatile(
        "mma.sync.aligned.m16n8k16.row.col.f32.bf16.bf16.f32 "
        "{%0,%1,%2,%3}, {%4,%5,%6,%7}, {%8,%9}, {%0,%1,%2,%3};"
        : "+f"(c[0]), "+f"(c[1]), "+f"(c[2]), "+f"(c[3])
        : "r"(a[0]), "r"(a[1]), "r"(a[2]), "r"(a[3]), "r"(b0), "r"(b1));
}
__device__ __forceinline__ void cp16(uint32_t dst, const void* src) {
    asm volatile("cp.async.cg.shared.global [%0], [%1], 16;" :: "r"(dst), "l"(src));
}
#define CP_COMMIT() asm volatile("cp.async.commit_group;" ::: "memory")
#define CP_WAIT0()  asm volatile("cp.async.wait_group 0;" ::: "memory")

// split float2 -> packed bf16 hi / lo
__device__ __forceinline__ void bsplit(float2 w, uint32_t& h, uint32_t& l) {
    __nv_bfloat162 hh, ll;
    hh.x = __float2bfloat16(w.x);
    hh.y = __float2bfloat16(w.y);
    ll.x = __float2bfloat16(w.x - __bfloat162float(hh.x));
    ll.y = __float2bfloat16(w.y - __bfloat162float(hh.y));
    h = *(uint32_t*)&hh;
    l = *(uint32_t*)&ll;
}

// ---------------- CSR build ----------------
__global__ void k_hist(const int* __restrict__ ed) {
    int e = blockIdx.x * blockDim.x + threadIdx.x;
    if (e < NE) atomicAdd(&g_deg[ed[e]], 1);
}
__global__ void k_scanA() {
    int b = blockIdx.x, t = threadIdx.x, i = b * 256 + t;
    int v = (i < NN) ? g_deg[i] : 0;
    int lane = t & 31, w = t >> 5;
    int x = v;
#pragma unroll
    for (int off = 1; off < 32; off <<= 1) {
        int y = __shfl_up_sync(0xffffffffu, x, off);
        if (lane >= off) x += y;
    }
    __shared__ int ws[8];
    if (lane == 31) ws[w] = x;
    __syncthreads();
    int add = 0;
#pragma unroll
    for (int j = 0; j < 8; j++) if (j < w) add += ws[j];
    x += add;
    if (i < NN) g_ptr[i] = x;
    if (t == 255) g_bsum[b] = x;
}
__global__ void k_fillB(const int* __restrict__ es, const int* __restrict__ ed,
                        const int* __restrict__ et, const float* __restrict__ ew) {
    __shared__ int sc[256];
    __shared__ int sOff[NBLK + 1];
    int t = threadIdx.x, b = blockIdx.x;
    int v = (t < NBLK) ? g_bsum[t] : 0;
    sc[t] = v;
    __syncthreads();
#pragma unroll
    for (int off = 1; off < 256; off <<= 1) {
        int u = (t >= off) ? sc[t - off] : 0;
        __syncthreads();
        sc[t] += u;
        __syncthreads();
    }
    if (t < NBLK) sOff[t] = sc[t] - v;
    if (t == NBLK - 1) sOff[NBLK] = sc[t];
    __syncthreads();
    int i = b * 256 + t;
    if (i < NN) g_ptr2[i] = g_ptr[i] - g_deg[i] + sOff[i >> 8];
    if (i == 0) g_ptr2[NN] = sOff[NBLK];
    int e = b * 256 + t;
    if (e < NE) {
        int d = ed[e];
        int base = g_ptr[d] - g_deg[d] + sOff[d >> 8];
        int p = atomicAdd(&g_pos[d], 1);
        int slot = base + p;
        g_ssrc[slot] = es[e];
        g_srel[slot] = et[e];
        g_sw[slot] = ew[e];
    }
}
__global__ void k_scale_partial() {
    __shared__ float sh[512];
    int t = threadIdx.x;
    int i = blockIdx.x * 512 + t;
    float v = (i < NN) ? logf((float)g_deg[i] + 1.0f) : 0.0f;
    sh[t] = v;
    __syncthreads();
    for (int off = 256; off > 0; off >>= 1) {
        if (t < off) sh[t] += sh[t + off];
        __syncthreads();
    }
    if (t == 0) g_partial[blockIdx.x] = sh[0];
}
__global__ void k_scale_finwrite() {
    __shared__ float sh[256];
    int t = threadIdx.x;
    sh[t] = (t < NB_SCALE) ? g_partial[t] : 0.0f;
    __syncthreads();
    for (int off = 128; off > 0; off >>= 1) {
        if (t < off) sh[t] += sh[t + off];
        __syncthreads();
    }
    float factor = (float)NN / sh[0];
    int i = blockIdx.x * 256 + t;
    if (i < NN) g_scale[i] = logf((float)g_deg[i] + 1.0f) * factor;
}

// ---------------- weight prep: smem transpose + bf16 split ----------------
__global__ void k_prepw(const float* __restrict__ linw) {
    __shared__ float ts[64][129];
    int tile = blockIdx.x;
    int l = tile / NCHUNK, kt = tile - l * NCHUNK;
    const float* src = linw + ((size_t)l * 1664 + kt * 64) * 128;
    for (int i = threadIdx.x; i < 8192; i += 256) {
        int k = i >> 7, n = i & 127;
        ts[k][n] = src[i];
    }
    __syncthreads();
    __nv_bfloat16* bh = g_Bhi + (size_t)tile * 8192;
    __nv_bfloat16* bl = g_Blo + (size_t)tile * 8192;
    for (int i = threadIdx.x; i < 8192; i += 256) {
        int n = i >> 6, kk = i & 63;
        float w = ts[kk][n];
        __nv_bfloat16 h = __float2bfloat16(w);
        bh[i] = h;
        bl[i] = __float2bfloat16(w - __bfloat162float(h));
    }
}

// ---------------- aggregation (R5 version, measured near L2 roofline) ----------------
__global__ void k_aggregate(const float* __restrict__ x, const float* __restrict__ x0,
                            const float* __restrict__ relw) {
    int gw = (blockIdx.x * blockDim.x + threadIdx.x) >> 5;
    int lane = threadIdx.x & 31;
    if (gw >= NN) return;
    int n = gw;
    float4 b = ((const float4*)(x0 + (size_t)n * DD))[lane];
    float4 sum = b, mx = b, mn = b;
    float4 ssq = make_float4(b.x * b.x, b.y * b.y, b.z * b.z, b.w * b.w);
    int p0 = g_ptr2[n], p1 = g_ptr2[n + 1];

    float4 xa, ra, xb, rb;
    float wa = 0.f, wb = 0.f;
    if (p0 < p1) {
        int s = g_ssrc[p0], r = g_srel[p0];
        wa = g_sw[p0];
        xa = ((const float4*)(x + (size_t)s * DD))[lane];
        ra = ((const float4*)(relw + (size_t)r * DD))[lane];
    }
    if (p0 + 1 < p1) {
        int s = g_ssrc[p0 + 1], r = g_srel[p0 + 1];
        wb = g_sw[p0 + 1];
        xb = ((const float4*)(x + (size_t)s * DD))[lane];
        rb = ((const float4*)(relw + (size_t)r * DD))[lane];
    }

#define ACCUM(xv, rv, wv) do { \
        float4 m = make_float4(xv.x * rv.x * wv, xv.y * rv.y * wv, xv.z * rv.z * wv, xv.w * rv.w * wv); \
        sum.x += m.x; sum.y += m.y; sum.z += m.z; sum.w += m.w; \
        ssq.x += m.x * m.x; ssq.y += m.y * m.y; ssq.z += m.z * m.z; ssq.w += m.w * m.w; \
        mx.x = fmaxf(mx.x, m.x); mx.y = fmaxf(mx.y, m.y); mx.z = fmaxf(mx.z, m.z); mx.w = fmaxf(mx.w, m.w); \
        mn.x = fminf(mn.x, m.x); mn.y = fminf(mn.y, m.y); mn.z = fminf(mn.z, m.z); mn.w = fminf(mn.w, m.w); \
    } while (0)

    int p = p0;
    while (p + 2 <= p1) {
        float4 cxa = xa, cra = ra, cxb = xb, crb = rb;
        float cwa = wa, cwb = wb;
        if (p + 2 < p1) {
            int s = g_ssrc[p + 2], r = g_srel[p + 2];
            wa = g_sw[p + 2];
            xa = ((const float4*)(x + (size_t)s * DD))[lane];
            ra = ((const float4*)(relw + (size_t)r * DD))[lane];
        }
        if (p + 3 < p1) {
            int s = g_ssrc[p + 3], r = g_srel[p + 3];
            wb = g_sw[p + 3];
            xb = ((const float4*)(x + (size_t)s * DD))[lane];
            rb = ((const float4*)(relw + (size_t)r * DD))[lane];
        }
        ACCUM(cxa, cra, cwa);
        ACCUM(cxb, crb, cwb);
        p += 2;
    }
    if (p < p1) ACCUM(xa, ra, wa);

    float invd = 1.0f / (float)(p1 - p0 + 1);
    float4 mean = make_float4(sum.x * invd, sum.y * invd, sum.z * invd, sum.w * invd);
    float4 sq = make_float4(ssq.x * invd, ssq.y * invd, ssq.z * invd, ssq.w * invd);
    float4 sd;
    sd.x = sqrtf(fmaxf(sq.x - mean.x * mean.x, 1e-6f));
    sd.y = sqrtf(fmaxf(sq.y - mean.y * mean.y, 1e-6f));
    sd.z = sqrtf(fmaxf(sq.z - mean.z * mean.z, 1e-6f));
    sd.w = sqrtf(fmaxf(sq.w - mean.w * mean.w, 1e-6f));
    float4* out = (float4*)(g_feats + (size_t)n * 512);
    out[0 * 32 + lane] = mean;
    out[1 * 32 + lane] = mx;
    out[2 * 32 + lane] = mn;
    out[3 * 32 + lane] = sd;
#undef ACCUM
}

// ---------------- linear v3: A direct-to-fragment, B smem double-buffered ----------------
// 512 threads, 16 warps = 8(M) x 2(N); warp tile 16x64; CTA tile 128x128.
// smem: header 2688 B; B buffers: 2 x (BH 18432 + BL 18432).
#define SM_HDR 2688
#define BBUF 36864
#define ROWB 144
#define LIN_SMEM (SM_HDR + 2 * BBUF)   // 76416

__global__ void __launch_bounds__(512, 1) k_linear_mma(
    const float* __restrict__ feats, const float* __restrict__ xin,
    const __nv_bfloat16* __restrict__ Bh, const __nv_bfloat16* __restrict__ Bl,
    const float* __restrict__ bias, const float* __restrict__ gam,
    const float* __restrict__ bet, float* __restrict__ xout) {
    extern __shared__ char smem[];
    uint32_t sb = smem_u32(smem);
    float* shf = (float*)smem;
    int t = threadIdx.x, wid = t >> 5, lane = t & 31;
    int m0 = blockIdx.x * 128;
    int wm = wid >> 1, wn = wid & 1;
    int gid = lane >> 2, tig = lane & 3;

    if (t < 128) {
        int node = min(m0 + t, NN - 1);
        float s1 = g_scale[node];
        shf[t] = s1;
        shf[128 + t] = 1.0f / fmaxf(s1, 1e-2f);
        shf[256 + t] = bias[t];
        shf[384 + t] = gam[t];
        shf[512 + t] = bet[t];
    }
    __syncthreads();

    float acc[8][4];
#pragma unroll
    for (int i = 0; i < 8; i++)
#pragma unroll
        for (int q = 0; q < 4; q++) acc[i][q] = 0.0f;

    // B ldmatrix lane addressing
    int aidx = lane & 7, agrp = lane >> 3;
    int b_row = aidx + ((agrp & 2) ? 8 : 0);
    int b_kof = (agrp & 1) ? 8 : 0;

    // per-thread A rows (fragment-direct)
    int row0 = wm * 16 + gid;            // and row0+8
    int node0 = min(m0 + row0, NN - 1);
    int node1 = min(m0 + row0 + 8, NN - 1);

    float2 v[2][8];
    uint32_t ah[16], al[16];

#define ISSUE_B(kt) do { \
        const char* _bh = (const char*)(Bh + (size_t)(kt) * 8192); \
        const char* _bl = (const char*)(Bl + (size_t)(kt) * 8192); \
        uint32_t _bb = sb + SM_HDR + ((kt) & 1) * BBUF; \
        _Pragma("unroll") \
        for (int _q = 0; _q < 2; ++_q) { \
            int _i = t + _q * 512; \
            int _n = _i >> 3, _c = _i & 7; \
            cp16(_bb + _n * ROWB + _c * 16, _bh + _i * 16); \
            cp16(_bb + 18432 + _n * ROWB + _c * 16, _bl + _i * 16); \
        } \
    } while (0)

#define LOAD_V(kt) do { \
        int _c0 = (kt) * 64; \
        bool _isx = (_c0 >= 1536); \
        int _j = _c0 >> 9, _f = (_c0 >> 7) & 3, _ko = _c0 & 127; \
        const float* _b0 = _isx ? (xin + (size_t)node0 * 128 + (_c0 - 1536)) \
                                : (feats + (size_t)node0 * 512 + _f * 128 + _ko); \
        const float* _b1 = _isx ? (xin + (size_t)node1 * 128 + (_c0 - 1536)) \
                                : (feats + (size_t)node1 * 512 + _f * 128 + _ko); \
        float _s0 = (_isx || _j == 0) ? 1.0f : ((_j == 1) ? shf[row0] : shf[128 + row0]); \
        float _s1 = (_isx || _j == 0) ? 1.0f : ((_j == 1) ? shf[row0 + 8] : shf[128 + row0 + 8]); \
        _Pragma("unroll") \
        for (int _u = 0; _u < 8; ++_u) { \
            float2 _a = *(const float2*)(_b0 + 2 * tig + 8 * _u); \
            float2 _b = *(const float2*)(_b1 + 2 * tig + 8 * _u); \
            v[0][_u] = make_float2(_a.x * _s0, _a.y * _s0); \
            v[1][_u] = make_float2(_b.x * _s1, _b.y * _s1); \
        } \
    } while (0)

#define CVT_V() do { \
        _Pragma("unroll") \
        for (int _ks = 0; _ks < 4; ++_ks) { \
            bsplit(v[0][2 * _ks],     ah[_ks * 4 + 0], al[_ks * 4 + 0]); \
            bsplit(v[1][2 * _ks],     ah[_ks * 4 + 1], al[_ks * 4 + 1]); \
            bsplit(v[0][2 * _ks + 1], ah[_ks * 4 + 2], al[_ks * 4 + 2]); \
            bsplit(v[1][2 * _ks + 1], ah[_ks * 4 + 3], al[_ks * 4 + 3]); \
        } \
    } while (0)

    // prologue
    LOAD_V(0);
    ISSUE_B(0);
    CP_COMMIT();
    CVT_V();
    CP_WAIT0();
    __syncthreads();

    for (int kt = 0; kt < NCHUNK; ++kt) {
        if (kt + 1 < NCHUNK) {
            LOAD_V(kt + 1);
            ISSUE_B(kt + 1);
        }
        CP_COMMIT();
        uint32_t tb = sb + SM_HDR + (kt & 1) * BBUF;
#pragma unroll
        for (int ks = 0; ks < 4; ++ks) {
            int kb = ks * 16;
            uint32_t bfr[4];
#pragma unroll
            for (int bt = 0; bt < 4; ++bt) {
                uint32_t boff = (uint32_t)((wn * 64 + bt * 16 + b_row) * ROWB + (kb + b_kof) * 2);
                ldm_x4(tb + boff, bfr);
                mma16816(acc[bt * 2 + 0], &ah[ks * 4], bfr[0], bfr[1]);
                mma16816(acc[bt * 2 + 1], &ah[ks * 4], bfr[2], bfr[3]);
                mma16816(acc[bt * 2 + 0], &al[ks * 4], bfr[0], bfr[1]);
                mma16816(acc[bt * 2 + 1], &al[ks * 4], bfr[2], bfr[3]);
                ldm_x4(tb + 18432 + boff, bfr);
                mma16816(acc[bt * 2 + 0], &ah[ks * 4], bfr[0], bfr[1]);
                mma16816(acc[bt * 2 + 1], &ah[ks * 4], bfr[2], bfr[3]);
            }
        }
        if (kt + 1 < NCHUNK) CVT_V();
        CP_WAIT0();
        __syncthreads();
    }

    // ---- epilogue: stage C (reuse B smem), LN per row ----
    float* Cs = (float*)(smem + SM_HDR);  // [128][132]
#pragma unroll
    for (int nt = 0; nt < 8; ++nt) {
        int col = wn * 64 + nt * 8 + 2 * tig;
        *(float2*)(Cs + row0 * 132 + col) = make_float2(acc[nt][0], acc[nt][1]);
        *(float2*)(Cs + (row0 + 8) * 132 + col) = make_float2(acc[nt][2], acc[nt][3]);
    }
    __syncthreads();

    float4 b4 = *(const float4*)(shf + 256 + lane * 4);
    float4 g4 = *(const float4*)(shf + 384 + lane * 4);
    float4 be4 = *(const float4*)(shf + 512 + lane * 4);
    for (int r = wid; r < 128; r += 16) {
        int node = m0 + r;
        if (node >= NN) break;
        float4 vv = *(const float4*)(Cs + r * 132 + lane * 4);
        vv.x += b4.x; vv.y += b4.y; vv.z += b4.z; vv.w += b4.w;
        float s = vv.x + vv.y + vv.z + vv.w;
        float q = vv.x * vv.x + vv.y * vv.y + vv.z * vv.z + vv.w * vv.w;
#pragma unroll
        for (int off = 16; off > 0; off >>= 1) {
            s += __shfl_xor_sync(0xffffffffu, s, off);
            q += __shfl_xor_sync(0xffffffffu, q, off);
        }
        float mu = s * (1.0f / 128.0f);
        float var = q * (1.0f / 128.0f) - mu * mu;
        float rs = rsqrtf(var + 1e-5f);
        float4 xr = *(const float4*)(xin + (size_t)node * 128 + lane * 4);
        float4 o;
        o.x = fmaxf((vv.x - mu) * rs * g4.x + be4.x, 0.0f) + xr.x;
        o.y = fmaxf((vv.y - mu) * rs * g4.y + be4.y, 0.0f) + xr.y;
        o.z = fmaxf((vv.z - mu) * rs * g4.z + be4.z, 0.0f) + xr.z;
        o.w = fmaxf((vv.w - mu) * rs * g4.w + be4.w, 0.0f) + xr.w;
        *(float4*)(xout + (size_t)node * 128 + lane * 4) = o;
    }
}

// ---------------- DistMult scoring + state cleanup ----------------
__global__ void k_score(const float* __restrict__ x, const float* __restrict__ qw,
                        const int* __restrict__ src, const int* __restrict__ rel,
                        const int* __restrict__ dst, float* __restrict__ out) {
    int tid = blockIdx.x * blockDim.x + threadIdx.x;
    if (tid < NN) { g_deg[tid] = 0; g_pos[tid] = 0; }
    int i = tid >> 5;
    int lane = threadIdx.x & 31;
    if (i >= 32768) return;
    int s = src[i], r = rel[i], d = dst[i];
    float4 a = ((const float4*)(x + (size_t)s * DD))[lane];
    float4 q = ((const float4*)(qw + (size_t)r * DD))[lane];
    float4 b = ((const float4*)(x + (size_t)d * DD))[lane];
    float p = a.x * q.x * b.x + a.y * q.y * b.y + a.z * q.z * b.z + a.w * q.w * b.w;
#pragma unroll
    for (int off = 16; off > 0; off >>= 1) p += __shfl_xor_sync(0xffffffffu, p, off);
    if (lane == 0) out[i] = p;
}

// ---------------- launch ----------------
extern "C" void kernel_launch(void* const* d_in, const int* in_sizes, int n_in,
                              void* d_out, int out_size) {
    const float* x0   = (const float*)d_in[0];
    const int*   ei   = (const int*)d_in[1];
    const int*   etyp = (const int*)d_in[2];
    const float* ew   = (const float*)d_in[3];
    const float* relw = (const float*)d_in[4];
    const float* linw = (const float*)d_in[5];
    const float* linb = (const float*)d_in[6];
    const float* lng  = (const float*)d_in[7];
    const float* lnb  = (const float*)d_in[8];
    const float* qw   = (const float*)d_in[9];
    const int*   src  = (const int*)d_in[10];
    const int*   rel  = (const int*)d_in[11];
    const int*   dst  = (const int*)d_in[12];
    float* out = (float*)d_out;
    const int* es = ei;
    const int* ed = ei + NE;

    cudaFuncSetAttribute(k_linear_mma, cudaFuncAttributeMaxDynamicSharedMemorySize, LIN_SMEM);

    void *pa, *pb, *pf, *pbh, *pbl;
    cudaGetSymbolAddress(&pa, g_xa);
    cudaGetSymbolAddress(&pb, g_xb);
    cudaGetSymbolAddress(&pf, g_feats);
    cudaGetSymbolAddress(&pbh, g_Bhi);
    cudaGetSymbolAddress(&pbl, g_Blo);
    float* XA = (float*)pa;
    float* XB = (float*)pb;
    float* F  = (float*)pf;
    __nv_bfloat16* BH = (__nv_bfloat16*)pbh;
    __nv_bfloat16* BL = (__nv_bfloat16*)pbl;

    k_hist<<<1954, 256>>>(ed);
    k_scanA<<<NBLK, 256>>>();
    k_fillB<<<1954, 256>>>(es, ed, etyp, ew);
    k_aggregate<<<6250, 256>>>(x0, x0, relw);   // launch 3: profiled
    k_scale_partial<<<NB_SCALE, 512>>>();
    k_scale_finwrite<<<NBLK, 256>>>();
    k_prepw<<<4 * NCHUNK, 256>>>(linw);

    const float* xi = x0;
    float* xo = XA;
    for (int l = 0; l < 4; l++) {
        if (l > 0) k_aggregate<<<6250, 256>>>(xi, x0, relw + (size_t)l * 51 * 128);
        k_linear_mma<<<(NN + 127) / 128, 512, LIN_SMEM>>>(
            F, xi, BH + (size_t)l * NCHUNK * 8192, BL + (size_t)l * NCHUNK * 8192,
            linb + l * 128, lng + l * 128, lnb + l * 128, xo);
        xi = xo;
        xo = (xo == XA) ? XB : XA;
    }
    k_score<<<4096, 256>>>(xi, qw, src, rel, dst, out);
}

// round 9
// speedup vs baseline: 1.4886x; 1.4886x over previous
#include <cuda_runtime.h>
#include <cuda_fp16.h>
#include <math.h>
#include <stdint.h>

#define NN 50000
#define NE 500000
#define DD 128
#define NB_SCALE 98
#define NCHUNK 26
#define NBLK 196   // ceil(50000/256)

// ---------------- device scratch ----------------
__device__ int   g_deg[NN];
__device__ int   g_pos[NN];
__device__ int   g_ptr[NN];        // scanA: block-local inclusive
__device__ int   g_ptr2[NN + 1];   // global exclusive (final CSR)
__device__ int   g_bsum[NBLK];
__device__ int   g_ssrc[NE];
__device__ int   g_srel[NE];
__device__ float g_sw[NE];
__device__ float g_scale[NN];
__device__ float g_partial[128];
__device__ float g_feats[(size_t)NN * 512];
__device__ float g_xa[(size_t)NN * DD];
__device__ float g_xb[(size_t)NN * DD];
// transposed fp16 weight tiles (hi/lo split): [4 layers][26 chunks][128 n][64 k]
__device__ __half g_Bhi[4 * NCHUNK * 8192];
__device__ __half g_Blo[4 * NCHUNK * 8192];

__device__ __forceinline__ uint32_t smem_u32(const void* p) {
    uint32_t a;
    asm("{ .reg .u64 t; cvta.to.shared.u64 t, %1; cvt.u32.u64 %0, t; }" : "=r"(a) : "l"(p));
    return a;
}
__device__ __forceinline__ void ldm_x4(uint32_t addr, uint32_t* r) {
    asm volatile("ldmatrix.sync.aligned.m8n8.x4.shared.b16 {%0,%1,%2,%3}, [%4];"
                 : "=r"(r[0]), "=r"(r[1]), "=r"(r[2]), "=r"(r[3]) : "r"(addr));
}
__device__ __forceinline__ void mma16816(float* c, const uint32_t* a, uint32_t b0, uint32_t b1) {
    asm volatile(
        "mma.sync.aligned.m16n8k16.row.col.f32.f16.f16.f32 "
        "{%0,%1,%2,%3}, {%4,%5,%6,%7}, {%8,%9}, {%0,%1,%2,%3};"
        : "+f"(c[0]), "+f"(c[1]), "+f"(c[2]), "+f"(c[3])
        : "r"(a[0]), "r"(a[1]), "r"(a[2]), "r"(a[3]), "r"(b0), "r"(b1));
}
__device__ __forceinline__ void cp16(uint32_t dst, const void* src) {
    asm volatile("cp.async.cg.shared.global [%0], [%1], 16;" :: "r"(dst), "l"(src));
}
#define CP_COMMIT() asm volatile("cp.async.commit_group;" ::: "memory")
#define CP_WAIT0()  asm volatile("cp.async.wait_group 0;" ::: "memory")

// ---------------- CSR build ----------------
__global__ void k_hist(const int* __restrict__ ed) {
    int e = blockIdx.x * blockDim.x + threadIdx.x;
    if (e < NE) atomicAdd(&g_deg[ed[e]], 1);
}
__global__ void k_scanA() {
    int b = blockIdx.x, t = threadIdx.x, i = b * 256 + t;
    int v = (i < NN) ? g_deg[i] : 0;
    int lane = t & 31, w = t >> 5;
    int x = v;
#pragma unroll
    for (int off = 1; off < 32; off <<= 1) {
        int y = __shfl_up_sync(0xffffffffu, x, off);
        if (lane >= off) x += y;
    }
    __shared__ int ws[8];
    if (lane == 31) ws[w] = x;
    __syncthreads();
    int add = 0;
#pragma unroll
    for (int j = 0; j < 8; j++) if (j < w) add += ws[j];
    x += add;
    if (i < NN) g_ptr[i] = x;
    if (t == 255) g_bsum[b] = x;
}
__global__ void k_fillB(const int* __restrict__ es, const int* __restrict__ ed,
                        const int* __restrict__ et, const float* __restrict__ ew) {
    __shared__ int sc[256];
    __shared__ int sOff[NBLK + 1];
    int t = threadIdx.x, b = blockIdx.x;
    int v = (t < NBLK) ? g_bsum[t] : 0;
    sc[t] = v;
    __syncthreads();
#pragma unroll
    for (int off = 1; off < 256; off <<= 1) {
        int u = (t >= off) ? sc[t - off] : 0;
        __syncthreads();
        sc[t] += u;
        __syncthreads();
    }
    if (t < NBLK) sOff[t] = sc[t] - v;
    if (t == NBLK - 1) sOff[NBLK] = sc[t];
    __syncthreads();
    int i = b * 256 + t;
    if (i < NN) g_ptr2[i] = g_ptr[i] - g_deg[i] + sOff[i >> 8];
    if (i == 0) g_ptr2[NN] = sOff[NBLK];
    int e = b * 256 + t;
    if (e < NE) {
        int d = ed[e];
        int base = g_ptr[d] - g_deg[d] + sOff[d >> 8];
        int p = atomicAdd(&g_pos[d], 1);
        int slot = base + p;
        g_ssrc[slot] = es[e];
        g_srel[slot] = et[e];
        g_sw[slot] = ew[e];
    }
}
__global__ void k_scale_partial() {
    __shared__ float sh[512];
    int t = threadIdx.x;
    int i = blockIdx.x * 512 + t;
    float v = (i < NN) ? logf((float)g_deg[i] + 1.0f) : 0.0f;
    sh[t] = v;
    __syncthreads();
    for (int off = 256; off > 0; off >>= 1) {
        if (t < off) sh[t] += sh[t + off];
        __syncthreads();
    }
    if (t == 0) g_partial[blockIdx.x] = sh[0];
}
__global__ void k_scale_finwrite() {
    __shared__ float sh[256];
    int t = threadIdx.x;
    sh[t] = (t < NB_SCALE) ? g_partial[t] : 0.0f;
    __syncthreads();
    for (int off = 128; off > 0; off >>= 1) {
        if (t < off) sh[t] += sh[t + off];
        __syncthreads();
    }
    float factor = (float)NN / sh[0];
    int i = blockIdx.x * 256 + t;
    if (i < NN) g_scale[i] = logf((float)g_deg[i] + 1.0f) * factor;
}

// ---------------- weight prep: smem transpose + fp16 hi/lo split ----------------
__global__ void k_prepw(const float* __restrict__ linw) {
    __shared__ float ts[64][129];
    int tile = blockIdx.x;
    int l = tile / NCHUNK, kt = tile - l * NCHUNK;
    const float* src = linw + ((size_t)l * 1664 + kt * 64) * 128;
    for (int i = threadIdx.x; i < 8192; i += 256) {
        int k = i >> 7, n = i & 127;
        ts[k][n] = src[i];
    }
    __syncthreads();
    __half* bh = g_Bhi + (size_t)tile * 8192;
    __half* bl = g_Blo + (size_t)tile * 8192;
    for (int i = threadIdx.x; i < 8192; i += 256) {
        int n = i >> 6, kk = i & 63;
        float w = ts[kk][n];
        __half h = __float2half_rn(w);
        bh[i] = h;
        bl[i] = __float2half_rn(w - __half2float(h));
    }
}

// ---------------- aggregation: warp/node, depth-1 prefetch (R4 version) ----------------
__global__ void k_aggregate(const float* __restrict__ x, const float* __restrict__ x0,
                            const float* __restrict__ relw) {
    int gw = (blockIdx.x * blockDim.x + threadIdx.x) >> 5;
    int lane = threadIdx.x & 31;
    if (gw >= NN) return;
    int n = gw;
    float4 b = ((const float4*)(x0 + (size_t)n * DD))[lane];
    float4 sum = b, mx = b, mn = b;
    float4 ssq = make_float4(b.x * b.x, b.y * b.y, b.z * b.z, b.w * b.w);
    int p0 = g_ptr2[n], p1 = g_ptr2[n + 1];
    float4 xv, rv;
    float w = 0.f;
    if (p0 < p1) {
        int s = g_ssrc[p0], r = g_srel[p0];
        w = g_sw[p0];
        xv = ((const float4*)(x + (size_t)s * DD))[lane];
        rv = ((const float4*)(relw + (size_t)r * DD))[lane];
    }
    for (int p = p0; p < p1; ++p) {
        float4 cx = xv, cr = rv;
        float cw = w;
        if (p + 1 < p1) {
            int s2 = g_ssrc[p + 1], r2 = g_srel[p + 1];
            w = g_sw[p + 1];
            xv = ((const float4*)(x + (size_t)s2 * DD))[lane];
            rv = ((const float4*)(relw + (size_t)r2 * DD))[lane];
        }
        float4 m = make_float4(cx.x * cr.x * cw, cx.y * cr.y * cw, cx.z * cr.z * cw, cx.w * cr.w * cw);
        sum.x += m.x; sum.y += m.y; sum.z += m.z; sum.w += m.w;
        ssq.x += m.x * m.x; ssq.y += m.y * m.y; ssq.z += m.z * m.z; ssq.w += m.w * m.w;
        mx.x = fmaxf(mx.x, m.x); mx.y = fmaxf(mx.y, m.y); mx.z = fmaxf(mx.z, m.z); mx.w = fmaxf(mx.w, m.w);
        mn.x = fminf(mn.x, m.x); mn.y = fminf(mn.y, m.y); mn.z = fminf(mn.z, m.z); mn.w = fminf(mn.w, m.w);
    }
    float invd = 1.0f / (float)(p1 - p0 + 1);
    float4 mean = make_float4(sum.x * invd, sum.y * invd, sum.z * invd, sum.w * invd);
    float4 sq = make_float4(ssq.x * invd, ssq.y * invd, ssq.z * invd, ssq.w * invd);
    float4 sd;
    sd.x = sqrtf(fmaxf(sq.x - mean.x * mean.x, 1e-6f));
    sd.y = sqrtf(fmaxf(sq.y - mean.y * mean.y, 1e-6f));
    sd.z = sqrtf(fmaxf(sq.z - mean.z * mean.z, 1e-6f));
    sd.w = sqrtf(fmaxf(sq.w - mean.w * mean.w, 1e-6f));
    float4* out = (float4*)(g_feats + (size_t)n * 512);
    out[0 * 32 + lane] = mean;
    out[1 * 32 + lane] = mx;
    out[2 * 32 + lane] = mn;
    out[3 * 32 + lane] = sd;
}

// ---------------- linear v4: fp16 2-term (A single-rounded, B hi/lo) ----------------
// CTA 128x128, 256 thr, 8 warps 4(M)x2(N), warp tile 32x64, double-buffered.
// smem buffer: A 18432 | BH 18432 | BL 18432 = 55296/buf.
#define SM_HDR 4096
#define BUFSZ 55296
#define OF_A  0
#define OF_BH 18432
#define OF_BL 36864
#define ROWB 144
#define LIN_SMEM (SM_HDR + 2 * BUFSZ)   // 114688

__global__ void __launch_bounds__(256) k_linear_mma(
    const float* __restrict__ feats, const float* __restrict__ xin,
    const __half* __restrict__ Bh, const __half* __restrict__ Bl,
    const float* __restrict__ bias, const float* __restrict__ gam,
    const float* __restrict__ bet, float* __restrict__ xout) {
    extern __shared__ char smem[];
    uint32_t sb = smem_u32(smem);
    float* shf = (float*)smem;
    int t = threadIdx.x, wid = t >> 5, lane = t & 31;
    int m0 = blockIdx.x * 128;
    int wm = wid >> 1, wn = wid & 1;

    if (t < 128) {
        int node = min(m0 + t, NN - 1);
        float s1 = g_scale[node];
        shf[t] = s1;
        shf[128 + t] = 1.0f / fmaxf(s1, 1e-2f);
        shf[256 + t] = bias[t];
        shf[384 + t] = gam[t];
        shf[512 + t] = bet[t];
    }
    __syncthreads();

    float acc[2][8][4];
#pragma unroll
    for (int i = 0; i < 2; i++)
#pragma unroll
        for (int j = 0; j < 8; j++)
#pragma unroll
            for (int q = 0; q < 4; q++) acc[i][j][q] = 0.0f;

    // ldmatrix lane addressing
    int aidx = lane & 7, agrp = lane >> 3;
    int a_row = aidx + ((agrp & 1) ? 8 : 0);
    int a_kof = (agrp & 2) ? 8 : 0;
    int b_row = aidx + ((agrp & 2) ? 8 : 0);
    int b_kof = (agrp & 1) ? 8 : 0;

    float4 v[8];

#define BUFBASE(kt) (SM_HDR + ((kt) & 1) * BUFSZ)

#define ISSUE_B(kt) do { \
        const char* _bh = (const char*)(Bh + (size_t)(kt) * 8192); \
        const char* _bl = (const char*)(Bl + (size_t)(kt) * 8192); \
        uint32_t _bb = sb + BUFBASE(kt); \
        _Pragma("unroll") \
        for (int _q = 0; _q < 4; ++_q) { \
            int _i = t + _q * 256; \
            int _n = _i >> 3, _c = _i & 7; \
            cp16(_bb + OF_BH + _n * ROWB + _c * 16, _bh + _i * 16); \
            cp16(_bb + OF_BL + _n * ROWB + _c * 16, _bl + _i * 16); \
        } \
    } while (0)

#define LOAD_A(kt) do { \
        int _c0 = (kt) * 64; \
        bool _isx = (_c0 >= 1536); \
        int _f = (_c0 >> 7) & 3, _ko = _c0 & 127; \
        _Pragma("unroll") \
        for (int _it = 0; _it < 8; ++_it) { \
            int _e = t + _it * 256; \
            int _m = _e >> 4, _kk = (_e & 15) * 4; \
            int _node = min(m0 + _m, NN - 1); \
            const float* _sr = _isx ? (xin + (size_t)_node * 128 + (_c0 - 1536) + _kk) \
                                    : (feats + (size_t)_node * 512 + _f * 128 + _ko + _kk); \
            v[_it] = *(const float4*)_sr; \
        } \
    } while (0)

#define STORE_A(kt) do { \
        int _c0 = (kt) * 64; \
        int _j = _c0 >> 9; \
        bool _isx = (_c0 >= 1536); \
        char* _ab = smem + BUFBASE(kt); \
        _Pragma("unroll") \
        for (int _it = 0; _it < 8; ++_it) { \
            int _e = t + _it * 256; \
            int _m = _e >> 4, _kk = (_e & 15) * 4; \
            float _sm = (_isx || _j == 0) ? 1.0f : ((_j == 1) ? shf[_m] : shf[128 + _m]); \
            float4 _w = v[_it]; \
            __half2 _h0 = __floats2half2_rn(_w.x * _sm, _w.y * _sm); \
            __half2 _h1 = __floats2half2_rn(_w.z * _sm, _w.w * _sm); \
            uint2 _u; \
            _u.x = *(uint32_t*)&_h0; \
            _u.y = *(uint32_t*)&_h1; \
            *(uint2*)(_ab + OF_A + _m * ROWB + _kk * 2) = _u; \
        } \
    } while (0)

    LOAD_A(0);
    ISSUE_B(0);
    CP_COMMIT();
    STORE_A(0);
    CP_WAIT0();
    __syncthreads();

    for (int kt = 0; kt < NCHUNK; ++kt) {
        if (kt + 1 < NCHUNK) {
            LOAD_A(kt + 1);
            ISSUE_B(kt + 1);
        }
        CP_COMMIT();
        uint32_t tb = sb + BUFBASE(kt);
#pragma unroll
        for (int ks = 0; ks < 4; ++ks) {
            int kb = ks * 16;
            uint32_t ah[8], bfr[4];
            uint32_t a_off = (uint32_t)((wm * 32 + a_row) * ROWB + (kb + a_kof) * 2);
            ldm_x4(tb + OF_A + a_off, ah);
            ldm_x4(tb + OF_A + a_off + 16 * ROWB, ah + 4);
#pragma unroll
            for (int nt = 0; nt < 4; ++nt) {
                uint32_t b_off = (uint32_t)((wn * 64 + nt * 16 + b_row) * ROWB + (kb + b_kof) * 2);
                ldm_x4(tb + OF_BH + b_off, bfr);
                mma16816(acc[0][2 * nt], ah, bfr[0], bfr[1]);
                mma16816(acc[0][2 * nt + 1], ah, bfr[2], bfr[3]);
                mma16816(acc[1][2 * nt], ah + 4, bfr[0], bfr[1]);
                mma16816(acc[1][2 * nt + 1], ah + 4, bfr[2], bfr[3]);
                ldm_x4(tb + OF_BL + b_off, bfr);
                mma16816(acc[0][2 * nt], ah, bfr[0], bfr[1]);
                mma16816(acc[0][2 * nt + 1], ah, bfr[2], bfr[3]);
                mma16816(acc[1][2 * nt], ah + 4, bfr[0], bfr[1]);
                mma16816(acc[1][2 * nt + 1], ah + 4, bfr[2], bfr[3]);
            }
        }
        if (kt + 1 < NCHUNK) STORE_A(kt + 1);
        CP_WAIT0();
        __syncthreads();
    }

    // ---- epilogue: stage C, LN per row ----
    float* Cs = (float*)(smem + SM_HDR);  // [128][132]
    int g = lane >> 2, l2 = (lane & 3) * 2;
#pragma unroll
    for (int mi = 0; mi < 2; ++mi)
#pragma unroll
        for (int ni = 0; ni < 8; ++ni) {
            int row = wm * 32 + mi * 16 + g;
            int col = wn * 64 + ni * 8 + l2;
            *(float2*)(Cs + row * 132 + col) = make_float2(acc[mi][ni][0], acc[mi][ni][1]);
            *(float2*)(Cs + (row + 8) * 132 + col) = make_float2(acc[mi][ni][2], acc[mi][ni][3]);
        }
    __syncthreads();

    float4 b4 = *(const float4*)(shf + 256 + lane * 4);
    float4 g4 = *(const float4*)(shf + 384 + lane * 4);
    float4 be4 = *(const float4*)(shf + 512 + lane * 4);
    for (int r = wid; r < 128; r += 8) {
        int node = m0 + r;
        if (node >= NN) break;
        float4 vv = *(const float4*)(Cs + r * 132 + lane * 4);
        vv.x += b4.x; vv.y += b4.y; vv.z += b4.z; vv.w += b4.w;
        float s = vv.x + vv.y + vv.z + vv.w;
        float q = vv.x * vv.x + vv.y * vv.y + vv.z * vv.z + vv.w * vv.w;
#pragma unroll
        for (int off = 16; off > 0; off >>= 1) {
            s += __shfl_xor_sync(0xffffffffu, s, off);
            q += __shfl_xor_sync(0xffffffffu, q, off);
        }
        float mu = s * (1.0f / 128.0f);
        float var = q * (1.0f / 128.0f) - mu * mu;
        float rs = rsqrtf(var + 1e-5f);
        float4 xr = *(const float4*)(xin + (size_t)node * 128 + lane * 4);
        float4 o;
        o.x = fmaxf((vv.x - mu) * rs * g4.x + be4.x, 0.0f) + xr.x;
        o.y = fmaxf((vv.y - mu) * rs * g4.y + be4.y, 0.0f) + xr.y;
        o.z = fmaxf((vv.z - mu) * rs * g4.z + be4.z, 0.0f) + xr.z;
        o.w = fmaxf((vv.w - mu) * rs * g4.w + be4.w, 0.0f) + xr.w;
        *(float4*)(xout + (size_t)node * 128 + lane * 4) = o;
    }
}

// ---------------- DistMult scoring + state cleanup ----------------
__global__ void k_score(const float* __restrict__ x, const float* __restrict__ qw,
                        const int* __restrict__ src, const int* __restrict__ rel,
                        const int* __restrict__ dst, float* __restrict__ out) {
    int tid = blockIdx.x * blockDim.x + threadIdx.x;
    if (tid < NN) { g_deg[tid] = 0; g_pos[tid] = 0; }
    int i = tid >> 5;
    int lane = threadIdx.x & 31;
    if (i >= 32768) return;
    int s = src[i], r = rel[i], d = dst[i];
    float4 a = ((const float4*)(x + (size_t)s * DD))[lane];
    float4 q = ((const float4*)(qw + (size_t)r * DD))[lane];
    float4 b = ((const float4*)(x + (size_t)d * DD))[lane];
    float p = a.x * q.x * b.x + a.y * q.y * b.y + a.z * q.z * b.z + a.w * q.w * b.w;
#pragma unroll
    for (int off = 16; off > 0; off >>= 1) p += __shfl_xor_sync(0xffffffffu, p, off);
    if (lane == 0) out[i] = p;
}

// ---------------- launch ----------------
extern "C" void kernel_launch(void* const* d_in, const int* in_sizes, int n_in,
                              void* d_out, int out_size) {
    const float* x0   = (const float*)d_in[0];
    const int*   ei   = (const int*)d_in[1];
    const int*   etyp = (const int*)d_in[2];
    const float* ew   = (const float*)d_in[3];
    const float* relw = (const float*)d_in[4];
    const float* linw = (const float*)d_in[5];
    const float* linb = (const float*)d_in[6];
    const float* lng  = (const float*)d_in[7];
    const float* lnb  = (const float*)d_in[8];
    const float* qw   = (const float*)d_in[9];
    const int*   src  = (const int*)d_in[10];
    const int*   rel  = (const int*)d_in[11];
    const int*   dst  = (const int*)d_in[12];
    float* out = (float*)d_out;
    const int* es = ei;
    const int* ed = ei + NE;

    cudaFuncSetAttribute(k_linear_mma, cudaFuncAttributeMaxDynamicSharedMemorySize, LIN_SMEM);

    void *pa, *pb, *pf, *pbh, *pbl;
    cudaGetSymbolAddress(&pa, g_xa);
    cudaGetSymbolAddress(&pb, g_xb);
    cudaGetSymbolAddress(&pf, g_feats);
    cudaGetSymbolAddress(&pbh, g_Bhi);
    cudaGetSymbolAddress(&pbl, g_Blo);
    float* XA = (float*)pa;
    float* XB = (float*)pb;
    float* F  = (float*)pf;
    __half* BH = (__half*)pbh;
    __half* BL = (__half*)pbl;

    k_hist<<<1954, 256>>>(ed);
    k_scanA<<<NBLK, 256>>>();
    k_fillB<<<1954, 256>>>(es, ed, etyp, ew);
    k_aggregate<<<6250, 256>>>(x0, x0, relw);   // launch 3: profiled
    k_scale_partial<<<NB_SCALE, 512>>>();
    k_scale_finwrite<<<NBLK, 256>>>();
    k_prepw<<<4 * NCHUNK, 256>>>(linw);

    const float* xi = x0;
    float* xo = XA;
    for (int l = 0; l < 4; l++) {
        if (l > 0) k_aggregate<<<6250, 256>>>(xi, x0, relw + (size_t)l * 51 * 128);
        k_linear_mma<<<(NN + 127) / 128, 256, LIN_SMEM>>>(
            F, xi, BH + (size_t)l * NCHUNK * 8192, BL + (size_t)l * NCHUNK * 8192,
            linb + l * 128, lng + l * 128, lnb + l * 128, xo);
        xi = xo;
        xo = (xo == XA) ? XB : XA;
    }
    k_score<<<4096, 256>>>(xi, qw, src, rel, dst, out);
}

// round 10
// speedup vs baseline: 2.1976x; 1.4763x over previous
#include <cuda_runtime.h>
#include <cuda_fp16.h>
#include <math.h>
#include <stdint.h>

#define NN 50000
#define NE 500000
#define DD 128
#define NB_SCALE 98
#define NCHUNK 26
#define NBLK 196   // ceil(50000/256)

// ---------------- device scratch ----------------
__device__ int   g_deg[NN];
__device__ int   g_pos[NN];
__device__ int   g_ptr[NN];        // scanA: block-local inclusive
__device__ int   g_ptr2[NN + 1];   // global exclusive (final CSR)
__device__ int   g_bsum[NBLK];
__device__ int   g_ssrc[NE];
__device__ int   g_srel[NE];
__device__ float g_sw[NE];
__device__ float g_scale[NN];
__device__ float g_partial[128];
__device__ float g_feats[(size_t)NN * 512];
__device__ float g_xa[(size_t)NN * DD];
__device__ float g_xb[(size_t)NN * DD];
// transposed fp16 weight tiles: [4 layers][26 chunks][128 n][64 k]
__device__ __half g_Bhi[4 * NCHUNK * 8192];

__device__ __forceinline__ uint32_t smem_u32(const void* p) {
    uint32_t a;
    asm("{ .reg .u64 t; cvta.to.shared.u64 t, %1; cvt.u32.u64 %0, t; }" : "=r"(a) : "l"(p));
    return a;
}
__device__ __forceinline__ void ldm_x4(uint32_t addr, uint32_t* r) {
    asm volatile("ldmatrix.sync.aligned.m8n8.x4.shared.b16 {%0,%1,%2,%3}, [%4];"
                 : "=r"(r[0]), "=r"(r[1]), "=r"(r[2]), "=r"(r[3]) : "r"(addr));
}
__device__ __forceinline__ void mma16816(float* c, const uint32_t* a, uint32_t b0, uint32_t b1) {
    asm volatile(
        "mma.sync.aligned.m16n8k16.row.col.f32.f16.f16.f32 "
        "{%0,%1,%2,%3}, {%4,%5,%6,%7}, {%8,%9}, {%0,%1,%2,%3};"
        : "+f"(c[0]), "+f"(c[1]), "+f"(c[2]), "+f"(c[3])
        : "r"(a[0]), "r"(a[1]), "r"(a[2]), "r"(a[3]), "r"(b0), "r"(b1));
}
__device__ __forceinline__ void cp16(uint32_t dst, const void* src) {
    asm volatile("cp.async.cg.shared.global [%0], [%1], 16;" :: "r"(dst), "l"(src));
}
#define CP_COMMIT() asm volatile("cp.async.commit_group;" ::: "memory")
#define CP_WAIT0()  asm volatile("cp.async.wait_group 0;" ::: "memory")

// ---------------- CSR build ----------------
__global__ void k_hist(const int* __restrict__ ed) {
    int e = blockIdx.x * blockDim.x + threadIdx.x;
    if (e < NE) atomicAdd(&g_deg[ed[e]], 1);
}
__global__ void k_scanA() {
    int b = blockIdx.x, t = threadIdx.x, i = b * 256 + t;
    int v = (i < NN) ? g_deg[i] : 0;
    int lane = t & 31, w = t >> 5;
    int x = v;
#pragma unroll
    for (int off = 1; off < 32; off <<= 1) {
        int y = __shfl_up_sync(0xffffffffu, x, off);
        if (lane >= off) x += y;
    }
    __shared__ int ws[8];
    if (lane == 31) ws[w] = x;
    __syncthreads();
    int add = 0;
#pragma unroll
    for (int j = 0; j < 8; j++) if (j < w) add += ws[j];
    x += add;
    if (i < NN) g_ptr[i] = x;
    if (t == 255) g_bsum[b] = x;
}
__global__ void k_fillB(const int* __restrict__ es, const int* __restrict__ ed,
                        const int* __restrict__ et, const float* __restrict__ ew) {
    __shared__ int sc[256];
    __shared__ int sOff[NBLK + 1];
    int t = threadIdx.x, b = blockIdx.x;
    int v = (t < NBLK) ? g_bsum[t] : 0;
    sc[t] = v;
    __syncthreads();
#pragma unroll
    for (int off = 1; off < 256; off <<= 1) {
        int u = (t >= off) ? sc[t - off] : 0;
        __syncthreads();
        sc[t] += u;
        __syncthreads();
    }
    if (t < NBLK) sOff[t] = sc[t] - v;
    if (t == NBLK - 1) sOff[NBLK] = sc[t];
    __syncthreads();
    int i = b * 256 + t;
    if (i < NN) g_ptr2[i] = g_ptr[i] - g_deg[i] + sOff[i >> 8];
    if (i == 0) g_ptr2[NN] = sOff[NBLK];
    int e = b * 256 + t;
    if (e < NE) {
        int d = ed[e];
        int base = g_ptr[d] - g_deg[d] + sOff[d >> 8];
        int p = atomicAdd(&g_pos[d], 1);
        int slot = base + p;
        g_ssrc[slot] = es[e];
        g_srel[slot] = et[e];
        g_sw[slot] = ew[e];
    }
}
__global__ void k_scale_partial() {
    __shared__ float sh[512];
    int t = threadIdx.x;
    int i = blockIdx.x * 512 + t;
    float v = (i < NN) ? logf((float)g_deg[i] + 1.0f) : 0.0f;
    sh[t] = v;
    __syncthreads();
    for (int off = 256; off > 0; off >>= 1) {
        if (t < off) sh[t] += sh[t + off];
        __syncthreads();
    }
    if (t == 0) g_partial[blockIdx.x] = sh[0];
}
__global__ void k_scale_finwrite() {
    __shared__ float sh[256];
    int t = threadIdx.x;
    sh[t] = (t < NB_SCALE) ? g_partial[t] : 0.0f;
    __syncthreads();
    for (int off = 128; off > 0; off >>= 1) {
        if (t < off) sh[t] += sh[t + off];
        __syncthreads();
    }
    float factor = (float)NN / sh[0];
    int i = blockIdx.x * 256 + t;
    if (i < NN) g_scale[i] = logf((float)g_deg[i] + 1.0f) * factor;
}

// ---------------- weight prep: smem transpose + fp16 ----------------
__global__ void k_prepw(const float* __restrict__ linw) {
    __shared__ float ts[64][129];
    int tile = blockIdx.x;
    int l = tile / NCHUNK, kt = tile - l * NCHUNK;
    const float* src = linw + ((size_t)l * 1664 + kt * 64) * 128;
    for (int i = threadIdx.x; i < 8192; i += 256) {
        int k = i >> 7, n = i & 127;
        ts[k][n] = src[i];
    }
    __syncthreads();
    __half* bh = g_Bhi + (size_t)tile * 8192;
    for (int i = threadIdx.x; i < 8192; i += 256) {
        int n = i >> 6, kk = i & 63;
        bh[i] = __float2half_rn(ts[kk][n]);
    }
}

// ---------------- aggregation: warp/node, depth-1 prefetch ----------------
__global__ void k_aggregate(const float* __restrict__ x, const float* __restrict__ x0,
                            const float* __restrict__ relw) {
    int gw = (blockIdx.x * blockDim.x + threadIdx.x) >> 5;
    int lane = threadIdx.x & 31;
    if (gw >= NN) return;
    int n = gw;
    float4 b = ((const float4*)(x0 + (size_t)n * DD))[lane];
    float4 sum = b, mx = b, mn = b;
    float4 ssq = make_float4(b.x * b.x, b.y * b.y, b.z * b.z, b.w * b.w);
    int p0 = g_ptr2[n], p1 = g_ptr2[n + 1];
    float4 xv, rv;
    float w = 0.f;
    if (p0 < p1) {
        int s = g_ssrc[p0], r = g_srel[p0];
        w = g_sw[p0];
        xv = ((const float4*)(x + (size_t)s * DD))[lane];
        rv = ((const float4*)(relw + (size_t)r * DD))[lane];
    }
    for (int p = p0; p < p1; ++p) {
        float4 cx = xv, cr = rv;
        float cw = w;
        if (p + 1 < p1) {
            int s2 = g_ssrc[p + 1], r2 = g_srel[p + 1];
            w = g_sw[p + 1];
            xv = ((const float4*)(x + (size_t)s2 * DD))[lane];
            rv = ((const float4*)(relw + (size_t)r2 * DD))[lane];
        }
        float4 m = make_float4(cx.x * cr.x * cw, cx.y * cr.y * cw, cx.z * cr.z * cw, cx.w * cr.w * cw);
        sum.x += m.x; sum.y += m.y; sum.z += m.z; sum.w += m.w;
        ssq.x += m.x * m.x; ssq.y += m.y * m.y; ssq.z += m.z * m.z; ssq.w += m.w * m.w;
        mx.x = fmaxf(mx.x, m.x); mx.y = fmaxf(mx.y, m.y); mx.z = fmaxf(mx.z, m.z); mx.w = fmaxf(mx.w, m.w);
        mn.x = fminf(mn.x, m.x); mn.y = fminf(mn.y, m.y); mn.z = fminf(mn.z, m.z); mn.w = fminf(mn.w, m.w);
    }
    float invd = 1.0f / (float)(p1 - p0 + 1);
    float4 mean = make_float4(sum.x * invd, sum.y * invd, sum.z * invd, sum.w * invd);
    float4 sq = make_float4(ssq.x * invd, ssq.y * invd, ssq.z * invd, ssq.w * invd);
    float4 sd;
    sd.x = sqrtf(fmaxf(sq.x - mean.x * mean.x, 1e-6f));
    sd.y = sqrtf(fmaxf(sq.y - mean.y * mean.y, 1e-6f));
    sd.z = sqrtf(fmaxf(sq.z - mean.z * mean.z, 1e-6f));
    sd.w = sqrtf(fmaxf(sq.w - mean.w * mean.w, 1e-6f));
    float4* out = (float4*)(g_feats + (size_t)n * 512);
    out[0 * 32 + lane] = mean;
    out[1 * 32 + lane] = mx;
    out[2 * 32 + lane] = mn;
    out[3 * 32 + lane] = sd;
}

// ---------------- linear v5: single-term fp16, 2 CTAs/SM ----------------
// CTA 128x128, 256 thr, 8 warps 4(M)x2(N), warp tile 32x64, double-buffered.
// smem buffer: A 18432 | BH 18432 = 36864/buf.
#define SM_HDR 4096
#define BUFSZ 36864
#define OF_A  0
#define OF_BH 18432
#define ROWB 144
#define LIN_SMEM (SM_HDR + 2 * BUFSZ)   // 77824

__global__ void __launch_bounds__(256, 2) k_linear_mma(
    const float* __restrict__ feats, const float* __restrict__ xin,
    const __half* __restrict__ Bh,
    const float* __restrict__ bias, const float* __restrict__ gam,
    const float* __restrict__ bet, float* __restrict__ xout) {
    extern __shared__ char smem[];
    uint32_t sb = smem_u32(smem);
    float* shf = (float*)smem;
    int t = threadIdx.x, wid = t >> 5, lane = t & 31;
    int m0 = blockIdx.x * 128;
    int wm = wid >> 1, wn = wid & 1;

    if (t < 128) {
        int node = min(m0 + t, NN - 1);
        float s1 = g_scale[node];
        shf[t] = s1;
        shf[128 + t] = 1.0f / fmaxf(s1, 1e-2f);
        shf[256 + t] = bias[t];
        shf[384 + t] = gam[t];
        shf[512 + t] = bet[t];
    }
    __syncthreads();

    float acc[2][8][4];
#pragma unroll
    for (int i = 0; i < 2; i++)
#pragma unroll
        for (int j = 0; j < 8; j++)
#pragma unroll
            for (int q = 0; q < 4; q++) acc[i][j][q] = 0.0f;

    // ldmatrix lane addressing
    int aidx = lane & 7, agrp = lane >> 3;
    int a_row = aidx + ((agrp & 1) ? 8 : 0);
    int a_kof = (agrp & 2) ? 8 : 0;
    int b_row = aidx + ((agrp & 2) ? 8 : 0);
    int b_kof = (agrp & 1) ? 8 : 0;

    float4 v[8];

#define BUFBASE(kt) (SM_HDR + ((kt) & 1) * BUFSZ)

#define ISSUE_B(kt) do { \
        const char* _bh = (const char*)(Bh + (size_t)(kt) * 8192); \
        uint32_t _bb = sb + BUFBASE(kt); \
        _Pragma("unroll") \
        for (int _q = 0; _q < 4; ++_q) { \
            int _i = t + _q * 256; \
            int _n = _i >> 3, _c = _i & 7; \
            cp16(_bb + OF_BH + _n * ROWB + _c * 16, _bh + _i * 16); \
        } \
    } while (0)

#define LOAD_A(kt) do { \
        int _c0 = (kt) * 64; \
        bool _isx = (_c0 >= 1536); \
        int _f = (_c0 >> 7) & 3, _ko = _c0 & 127; \
        _Pragma("unroll") \
        for (int _it = 0; _it < 8; ++_it) { \
            int _e = t + _it * 256; \
            int _m = _e >> 4, _kk = (_e & 15) * 4; \
            int _node = min(m0 + _m, NN - 1); \
            const float* _sr = _isx ? (xin + (size_t)_node * 128 + (_c0 - 1536) + _kk) \
                                    : (feats + (size_t)_node * 512 + _f * 128 + _ko + _kk); \
            v[_it] = *(const float4*)_sr; \
        } \
    } while (0)

#define STORE_A(kt) do { \
        int _c0 = (kt) * 64; \
        int _j = _c0 >> 9; \
        bool _isx = (_c0 >= 1536); \
        char* _ab = smem + BUFBASE(kt); \
        _Pragma("unroll") \
        for (int _it = 0; _it < 8; ++_it) { \
            int _e = t + _it * 256; \
            int _m = _e >> 4, _kk = (_e & 15) * 4; \
            float _sm = (_isx || _j == 0) ? 1.0f : ((_j == 1) ? shf[_m] : shf[128 + _m]); \
            float4 _w = v[_it]; \
            __half2 _h0 = __floats2half2_rn(_w.x * _sm, _w.y * _sm); \
            __half2 _h1 = __floats2half2_rn(_w.z * _sm, _w.w * _sm); \
            uint2 _u; \
            _u.x = *(uint32_t*)&_h0; \
            _u.y = *(uint32_t*)&_h1; \
            *(uint2*)(_ab + OF_A + _m * ROWB + _kk * 2) = _u; \
        } \
    } while (0)

    LOAD_A(0);
    ISSUE_B(0);
    CP_COMMIT();
    STORE_A(0);
    CP_WAIT0();
    __syncthreads();

    for (int kt = 0; kt < NCHUNK; ++kt) {
        if (kt + 1 < NCHUNK) {
            LOAD_A(kt + 1);
            ISSUE_B(kt + 1);
        }
        CP_COMMIT();
        uint32_t tb = sb + BUFBASE(kt);
#pragma unroll
        for (int ks = 0; ks < 4; ++ks) {
            int kb = ks * 16;
            uint32_t ah[8], bfr[4];
            uint32_t a_off = (uint32_t)((wm * 32 + a_row) * ROWB + (kb + a_kof) * 2);
            ldm_x4(tb + OF_A + a_off, ah);
            ldm_x4(tb + OF_A + a_off + 16 * ROWB, ah + 4);
#pragma unroll
            for (int nt = 0; nt < 4; ++nt) {
                uint32_t b_off = (uint32_t)((wn * 64 + nt * 16 + b_row) * ROWB + (kb + b_kof) * 2);
                ldm_x4(tb + OF_BH + b_off, bfr);
                mma16816(acc[0][2 * nt], ah, bfr[0], bfr[1]);
                mma16816(acc[0][2 * nt + 1], ah, bfr[2], bfr[3]);
                mma16816(acc[1][2 * nt], ah + 4, bfr[0], bfr[1]);
                mma16816(acc[1][2 * nt + 1], ah + 4, bfr[2], bfr[3]);
            }
        }
        if (kt + 1 < NCHUNK) STORE_A(kt + 1);
        CP_WAIT0();
        __syncthreads();
    }

    // ---- epilogue: stage C, LN per row ----
    float* Cs = (float*)(smem + SM_HDR);  // [128][132] = 67584 B, fits in 2*BUFSZ
    int g = lane >> 2, l2 = (lane & 3) * 2;
#pragma unroll
    for (int mi = 0; mi < 2; ++mi)
#pragma unroll
        for (int ni = 0; ni < 8; ++ni) {
            int row = wm * 32 + mi * 16 + g;
            int col = wn * 64 + ni * 8 + l2;
            *(float2*)(Cs + row * 132 + col) = make_float2(acc[mi][ni][0], acc[mi][ni][1]);
            *(float2*)(Cs + (row + 8) * 132 + col) = make_float2(acc[mi][ni][2], acc[mi][ni][3]);
        }
    __syncthreads();

    float4 b4 = *(const float4*)(shf + 256 + lane * 4);
    float4 g4 = *(const float4*)(shf + 384 + lane * 4);
    float4 be4 = *(const float4*)(shf + 512 + lane * 4);
    for (int r = wid; r < 128; r += 8) {
        int node = m0 + r;
        if (node >= NN) break;
        float4 vv = *(const float4*)(Cs + r * 132 + lane * 4);
        vv.x += b4.x; vv.y += b4.y; vv.z += b4.z; vv.w += b4.w;
        float s = vv.x + vv.y + vv.z + vv.w;
        float q = vv.x * vv.x + vv.y * vv.y + vv.z * vv.z + vv.w * vv.w;
#pragma unroll
        for (int off = 16; off > 0; off >>= 1) {
            s += __shfl_xor_sync(0xffffffffu, s, off);
            q += __shfl_xor_sync(0xffffffffu, q, off);
        }
        float mu = s * (1.0f / 128.0f);
        float var = q * (1.0f / 128.0f) - mu * mu;
        float rs = rsqrtf(var + 1e-5f);
        float4 xr = *(const float4*)(xin + (size_t)node * 128 + lane * 4);
        float4 o;
        o.x = fmaxf((vv.x - mu) * rs * g4.x + be4.x, 0.0f) + xr.x;
        o.y = fmaxf((vv.y - mu) * rs * g4.y + be4.y, 0.0f) + xr.y;
        o.z = fmaxf((vv.z - mu) * rs * g4.z + be4.z, 0.0f) + xr.z;
        o.w = fmaxf((vv.w - mu) * rs * g4.w + be4.w, 0.0f) + xr.w;
        *(float4*)(xout + (size_t)node * 128 + lane * 4) = o;
    }
}

// ---------------- DistMult scoring + state cleanup ----------------
__global__ void k_score(const float* __restrict__ x, const float* __restrict__ qw,
                        const int* __restrict__ src, const int* __restrict__ rel,
                        const int* __restrict__ dst, float* __restrict__ out) {
    int tid = blockIdx.x * blockDim.x + threadIdx.x;
    if (tid < NN) { g_deg[tid] = 0; g_pos[tid] = 0; }
    int i = tid >> 5;
    int lane = threadIdx.x & 31;
    if (i >= 32768) return;
    int s = src[i], r = rel[i], d = dst[i];
    float4 a = ((const float4*)(x + (size_t)s * DD))[lane];
    float4 q = ((const float4*)(qw + (size_t)r * DD))[lane];
    float4 b = ((const float4*)(x + (size_t)d * DD))[lane];
    float p = a.x * q.x * b.x + a.y * q.y * b.y + a.z * q.z * b.z + a.w * q.w * b.w;
#pragma unroll
    for (int off = 16; off > 0; off >>= 1) p += __shfl_xor_sync(0xffffffffu, p, off);
    if (lane == 0) out[i] = p;
}

// ---------------- launch ----------------
extern "C" void kernel_launch(void* const* d_in, const int* in_sizes, int n_in,
                              void* d_out, int out_size) {
    const float* x0   = (const float*)d_in[0];
    const int*   ei   = (const int*)d_in[1];
    const int*   etyp = (const int*)d_in[2];
    const float* ew   = (const float*)d_in[3];
    const float* relw = (const float*)d_in[4];
    const float* linw = (const float*)d_in[5];
    const float* linb = (const float*)d_in[6];
    const float* lng  = (const float*)d_in[7];
    const float* lnb  = (const float*)d_in[8];
    const float* qw   = (const float*)d_in[9];
    const int*   src  = (const int*)d_in[10];
    const int*   rel  = (const int*)d_in[11];
    const int*   dst  = (const int*)d_in[12];
    float* out = (float*)d_out;
    const int* es = ei;
    const int* ed = ei + NE;

    cudaFuncSetAttribute(k_linear_mma, cudaFuncAttributeMaxDynamicSharedMemorySize, LIN_SMEM);

    void *pa, *pb, *pf, *pbh;
    cudaGetSymbolAddress(&pa, g_xa);
    cudaGetSymbolAddress(&pb, g_xb);
    cudaGetSymbolAddress(&pf, g_feats);
    cudaGetSymbolAddress(&pbh, g_Bhi);
    float* XA = (float*)pa;
    float* XB = (float*)pb;
    float* F  = (float*)pf;
    __half* BH = (__half*)pbh;

    k_hist<<<1954, 256>>>(ed);
    k_scanA<<<NBLK, 256>>>();
    k_fillB<<<1954, 256>>>(es, ed, etyp, ew);
    k_aggregate<<<6250, 256>>>(x0, x0, relw);   // launch 3: profiled
    k_scale_partial<<<NB_SCALE, 512>>>();
    k_scale_finwrite<<<NBLK, 256>>>();
    k_prepw<<<4 * NCHUNK, 256>>>(linw);

    const float* xi = x0;
    float* xo = XA;
    for (int l = 0; l < 4; l++) {
        if (l > 0) k_aggregate<<<6250, 256>>>(xi, x0, relw + (size_t)l * 51 * 128);
        k_linear_mma<<<(NN + 127) / 128, 256, LIN_SMEM>>>(
            F, xi, BH + (size_t)l * NCHUNK * 8192,
            linb + l * 128, lng + l * 128, lnb + l * 128, xo);
        xi = xo;
        xo = (xo == XA) ? XB : XA;
    }
    k_score<<<4096, 256>>>(xi, qw, src, rel, dst, out);
}